// round 11
// baseline (speedup 1.0000x reference)
#include <cuda_runtime.h>
#include <math.h>

#define FEAT   64
#define EMBC   256
#define IMGSZ  1024
#define NCELLS 256
#define THRESH 0.65f
#define SCAN_BX 15
#define SCAN_BY 90
#define TILE_R  16
#define TILE_C  80
#define YCHUNK  32

// ---------------- device scratch (no allocations allowed) ----------------
__device__ float d_sim[FEAT * FEAT];
__device__ float4 d_xtab[4096];              // scan x-taps: {i0 (bits), w0, w1, 0}
__device__ float4 d_ytab[4096];              // scan y-taps: {i0 (bits), w0, w1, gy16 (bits)}
__device__ float4 d_xt1[1024];               // 64->1024 taps (P rows AND cols)
__device__ unsigned long long d_minkey;      // global argmin key
__device__ unsigned long long d_cellkey[NCELLS];
__device__ int d_counter;

// ---------------- ordered-float key helpers ----------------
__device__ __forceinline__ unsigned fkey(float f) {
    unsigned u = __float_as_uint(f);
    return (u >> 31) ? ~u : (u | 0x80000000u);   // monotone: smaller float -> smaller key
}
__device__ __forceinline__ float unfkey(unsigned k) {
    return (k & 0x80000000u) ? __uint_as_float(k & 0x7FFFFFFFu) : __uint_as_float(~k);
}

// ---------------- jax.image.resize (linear, antialias=False) fp-exact taps ----------------
struct Tap { int i0; float w0, w1; };

__device__ __forceinline__ float samplef(int o, float inv) {
    return __fsub_rn(__fmul_rn(__fadd_rn((float)o, 0.5f), inv), 0.5f);
}

__device__ __forceinline__ Tap make_tap(float s, int n) {
    Tap t;
    float fs = floorf(s);
    int i0 = (int)fs;
    if (i0 < 0)            { t.i0 = 0;     t.w0 = 1.f; t.w1 = 0.f; }
    else if (i0 >= n - 1)  { t.i0 = n - 2; t.w0 = 0.f; t.w1 = 1.f; }
    else {
        float w0  = __fsub_rn(1.0f, __fsub_rn(s, fs));
        float w1  = __fsub_rn(1.0f, __fsub_rn((float)(i0 + 1), s));
        float sum = __fadd_rn(w0, w1);
        if (sum != 1.0f) { w0 = __fdiv_rn(w0, sum); w1 = __fdiv_rn(w1, sum); }
        t.i0 = i0; t.w0 = w0; t.w1 = w1;
    }
    return t;
}

// ---------------- kernel 1: sim (8-way channel split) + all tap tables + init ----------------
__global__ void __launch_bounds__(256) k_simtab(const float* __restrict__ emb,
                                                const float* __restrict__ ref,
                                                const int* __restrict__ ori) {
    int t = threadIdx.x;
    if (blockIdx.x < 128) {
        __shared__ float sref[EMBC];
        __shared__ float sdot[256];
        __shared__ float snrm[256];
        sref[t] = ref[t];
        __syncthreads();

        int px = t & 31;
        int q  = t >> 5;                      // channel group 0..7
        int p  = (blockIdx.x << 5) + px;      // feature pixel
        const float* e = emb + (q * 32) * (FEAT * FEAT) + p;
        const float* r = sref + q * 32;
        float dot = 0.f, nrm = 0.f;
        #pragma unroll
        for (int j = 0; j < 32; j++) {
            float v = e[j * (FEAT * FEAT)];   // coalesced, 32 independent loads
            dot = fmaf(r[j], v, dot);
            nrm = fmaf(v, v, nrm);
        }
        sdot[t] = dot; snrm[t] = nrm;
        __syncthreads();

        if (t < 32) {
            float D = sdot[t], N = snrm[t];
            #pragma unroll
            for (int q2 = 1; q2 < 8; q2++) {  // fixed sequential order (deterministic)
                D += sdot[t + (q2 << 5)];
                N += snrm[t + (q2 << 5)];
            }
            d_sim[(blockIdx.x << 5) + t] = D / sqrtf(N);
        }
    } else {
        int idx = (blockIdx.x - 128) * 256 + t;   // 0..4095
        if (idx == 0) { d_minkey = ~0ull; d_counter = 0; }
        if (idx < NCELLS) d_cellkey[idx] = 0ull;

        if (idx < 1024) {                         // 64 -> 1024 taps (P rows and cols)
            Tap tp = make_tap(samplef(idx, 0.0625f), FEAT);
            d_xt1[idx] = make_float4(__int_as_float(tp.i0), tp.w0, tp.w1, 0.f);
        }
        int H = ori[0], W = ori[1];
        int mx = max(H, W);
        double scale = (double)IMGSZ / (double)mx;
        int ph = (int)floor((double)H * scale + 0.5);
        int pw = (int)floor((double)W * scale + 0.5);
        float invx = (float)(1.0 / ((double)W / (double)pw));
        float invy = (float)(1.0 / ((double)H / (double)ph));
        float r64  = (float)(scale / 64.0);
        if (idx < W) {                            // scan x-taps (pw -> W)
            Tap tp = make_tap(samplef(idx, invx), pw);
            d_xtab[idx] = make_float4(__int_as_float(tp.i0), tp.w0, tp.w1, 0.f);
        }
        if (idx < H) {                            // scan y-taps (ph -> H) + gy16
            Tap tp = make_tap(samplef(idx, invy), ph);
            int gy16 = 16 * (int)floorf(__fmul_rn((float)idx, r64));
            d_ytab[idx] = make_float4(__int_as_float(tp.i0), tp.w0, tp.w1,
                                      __int_as_float(gy16));
        }
    }
}

// ---------------- kernel 2: fused P-tile + column scan (4 indep min chains) + finalize ----------------
__global__ void __launch_bounds__(256) k_scan(const int* __restrict__ ori,
                                              float* __restrict__ out) {
    int H = ori[0], W = ori[1];
    int mx = max(H, W);
    double scale = (double)IMGSZ / (double)mx;
    float r64  = (float)(scale / 64.0);

    __shared__ float2 tile2[TILE_R][TILE_C];   // {P(r,c), P(r,c+1)} pairs
    __shared__ float  cys[TILE_R][12];         // y-contracted sim cols per P-row
    __shared__ float4 s_yt[YCHUNK];            // staged y-taps for this strip

    int t  = threadIdx.x;
    int xs = blockIdx.x * 256;
    int nby = gridDim.y;
    int chn = (H + nby - 1) / nby;             // <= YCHUNK
    int ys = blockIdx.y * chn;
    int ye = min(H, ys + chn);

    unsigned long long localkey = ~0ull;

    if (ys < H && xs < W) {
        int ny = ye - ys;
        int xe = min(xs + 256, W);
        // P-tile bounds this block needs (monotone tap tables)
        int pr0 = __float_as_int(d_ytab[ys].x);
        int pr1 = __float_as_int(d_ytab[ye - 1].x) + 1;
        int px0 = __float_as_int(d_xtab[xs].x);
        int px1 = __float_as_int(d_xtab[xe - 1].x) + 1;
        int NR = pr1 - pr0 + 1;            // <= 11
        int NC = px1 - px0 + 1;            // <= 71

        // stage y-taps for this strip
        for (int i = t; i < ny; i += 256) s_yt[i] = d_ytab[ys + i];

        // phase A: y-contractions over the few needed sim columns (exact expr)
        int xi0 = __float_as_int(d_xt1[px0].x);
        int xi1 = __float_as_int(d_xt1[px1].x);
        int NJ = xi1 - xi0 + 2;            // <= ~8
        for (int i = t; i < NR * NJ; i += 256) {
            int r = i / NJ, j = i - r * NJ;
            float4 tyr = d_xt1[pr0 + r];
            int yi = __float_as_int(tyr.x);
            const float* s0 = d_sim + yi * FEAT + xi0 + j;
            cys[r][j] = fmaf(tyr.z, s0[FEAT], __fmul_rn(tyr.y, s0[0]));
        }
        __syncthreads();

        // phase B: assemble tile2 from cys (bit-identical to p_val)
        int nbuild = NR * (NC - 1);
        for (int i = t; i < nbuild; i += 256) {
            int r = i / (NC - 1), c = i - r * (NC - 1);
            float4 t0 = d_xt1[px0 + c];
            float4 t1 = d_xt1[px0 + c + 1];
            int j0 = __float_as_int(t0.x) - xi0;
            int j1 = __float_as_int(t1.x) - xi0;
            float v0 = fmaf(t0.z, cys[r][j0 + 1], __fmul_rn(t0.y, cys[r][j0]));
            float v1 = fmaf(t1.z, cys[r][j1 + 1], __fmul_rn(t1.y, cys[r][j1]));
            tile2[r][c] = make_float2(v0, v1);
        }
        __syncthreads();

        int x = xs + t;
        if (x < W) {
            float4 tx = d_xtab[x];
            int   lx  = __float_as_int(tx.x) - px0;
            float wx0 = tx.y, wx1 = tx.z;
            int   gx  = (int)floorf(__fmul_rn((float)x, r64));

            // 4 independent min chains (j-th handles y = ys + 4k + j)
            float rb0 = INFINITY, rb1 = INFINITY, rb2 = INFINITY, rb3 = INFINITY;
            int   ri0 = 0, ri1 = 0, ri2 = 0, ri3 = 0;

            int idx0 = ys * W + x;
            int i = 0;
            for (; i + 3 < ny; i += 4) {
                #pragma unroll
                for (int j = 0; j < 4; j++) {
                    float4 ty = s_yt[i + j];
                    int lr = __float_as_int(ty.x) - pr0;
                    float2 A = tile2[lr][lx];
                    float2 B = tile2[lr + 1][lx];
                    float c0 = fmaf(ty.z, B.x, __fmul_rn(ty.y, A.x));
                    float c1 = fmaf(ty.z, B.y, __fmul_rn(ty.y, A.y));
                    float v  = fmaf(wx1, c1, __fmul_rn(wx0, c0));
                    int  idx = idx0 + j * W;

                    if (j == 0) { if (v < rb0) { rb0 = v; ri0 = idx; } }
                    if (j == 1) { if (v < rb1) { rb1 = v; ri1 = idx; } }
                    if (j == 2) { if (v < rb2) { rb2 = v; ri2 = idx; } }
                    if (j == 3) { if (v < rb3) { rb3 = v; ri3 = idx; } }

                    if (v > THRESH) {            // rare; exact semantics preserved
                        int cell = __float_as_int(ty.w) + gx;
                        unsigned long long ck = ((unsigned long long)fkey(v) << 32)
                                              | (unsigned)(0xFFFFFFFFu - (unsigned)idx);
                        atomicMax(&d_cellkey[cell], ck);
                    }
                }
                idx0 += 4 * W;
            }
            for (; i < ny; i++) {                // remainder -> chain 0 (idx still increasing)
                float4 ty = s_yt[i];
                int lr = __float_as_int(ty.x) - pr0;
                float2 A = tile2[lr][lx];
                float2 B = tile2[lr + 1][lx];
                float c0 = fmaf(ty.z, B.x, __fmul_rn(ty.y, A.x));
                float c1 = fmaf(ty.z, B.y, __fmul_rn(ty.y, A.y));
                float v  = fmaf(wx1, c1, __fmul_rn(wx0, c0));
                if (v < rb0) { rb0 = v; ri0 = idx0; }
                if (v > THRESH) {
                    int cell = __float_as_int(ty.w) + gx;
                    unsigned long long ck = ((unsigned long long)fkey(v) << 32)
                                          | (unsigned)(0xFFFFFFFFu - (unsigned)idx0);
                    atomicMax(&d_cellkey[cell], ck);
                }
                idx0 += W;
            }

            // merge chains via packed keys: bit-equal values -> lowest index wins
            unsigned long long k0 = ((unsigned long long)fkey(rb0) << 32) | (unsigned)ri0;
            unsigned long long k1 = ((unsigned long long)fkey(rb1) << 32) | (unsigned)ri1;
            unsigned long long k2 = ((unsigned long long)fkey(rb2) << 32) | (unsigned)ri2;
            unsigned long long k3 = ((unsigned long long)fkey(rb3) << 32) | (unsigned)ri3;
            localkey = min(min(k0, k1), min(k2, k3));
        }
    }

    // block argmin reduction
    __shared__ unsigned long long sk[256];
    __shared__ int s_last;
    sk[t] = localkey;
    __syncthreads();
    for (int o = 128; o > 0; o >>= 1) {
        if (t < o) sk[t] = min(sk[t], sk[t + o]);
        __syncthreads();
    }
    if (t == 0) {
        atomicMin(&d_minkey, sk[0]);
        __threadfence();
        s_last = (atomicAdd(&d_counter, 1) == (int)(gridDim.x * gridDim.y) - 1);
    }
    __syncthreads();
    if (!s_last) return;

    // ---- last block: finalize ----
    __shared__ float s_key[NCELLS];
    unsigned long long ck = atomicOr(&d_cellkey[t], 0ull);    // coherent read
    bool valid = (ck != 0ull);
    float ps = 0.f; int pidx = 0;
    if (valid) {
        ps   = unfkey((unsigned)(ck >> 32));
        pidx = (int)(0xFFFFFFFFu - (unsigned)(ck & 0xFFFFFFFFull));
    }
    float skey = valid ? ps : -INFINITY;
    s_key[t] = skey;
    __syncthreads();

    int rank = 0;
    #pragma unroll 8
    for (int j = 0; j < NCELLS; j++) {
        float o = s_key[j];
        rank += (o > skey) || (o == skey && j < t);
    }

    out[rank * 3 + 0] = valid ? (float)(pidx % W) : -1.f;
    out[rank * 3 + 1] = valid ? (float)(pidx / W) : -1.f;
    out[rank * 3 + 2] = valid ? ps : -1.f;

    if (t == 0) {
        unsigned long long mk = atomicOr(&d_minkey, 0ull);
        unsigned bidx = (unsigned)(mk & 0xFFFFFFFFull);
        out[NCELLS * 3 + 0] = (float)(bidx % (unsigned)W);   // bg col (x)
        out[NCELLS * 3 + 1] = (float)(bidx / (unsigned)W);   // bg row (y)
    }
}

// ---------------- launch ----------------
extern "C" void kernel_launch(void* const* d_in, const int* in_sizes, int n_in,
                              void* d_out, int out_size) {
    int ie = 0, ir = 1, io = 2;
    for (int i = 0; i < n_in; i++) {
        if (in_sizes[i] == 2) io = i;
        else if (in_sizes[i] == EMBC) ir = i;
        else ie = i;
    }
    const float* emb = (const float*)d_in[ie];
    const float* ref = (const float*)d_in[ir];
    const int*   ori = (const int*)d_in[io];
    float* out = (float*)d_out;

    k_simtab<<<144, 256>>>(emb, ref, ori);
    k_scan  <<<dim3(SCAN_BX, SCAN_BY), 256>>>(ori, out);
}

// round 12
// speedup vs baseline: 1.2146x; 1.2146x over previous
#include <cuda_runtime.h>
#include <math.h>

#define FEAT   64
#define EMBC   256
#define IMGSZ  1024
#define NCELLS 256
#define THRESH 0.65f
#define SCAN_BX 15
#define SCAN_BY 48
#define TILE_R  16
#define TILE_C  80
#define YCHUNK  96

// ---------------- device scratch (no allocations allowed) ----------------
__device__ float d_sim[FEAT * FEAT];
__device__ float4 d_xtab[4096];              // scan x-taps: {i0 (bits), w0, w1, 0}
__device__ float4 d_ytab[4096];              // scan y-taps: {i0 (bits), w0, w1, gy16 (bits)}
__device__ float4 d_xt1[1024];               // 64->1024 taps (P rows AND cols)
__device__ unsigned long long d_minkey;      // global argmin key
__device__ unsigned long long d_cellkey[NCELLS];
__device__ int d_counter;

// ---------------- ordered-float key helpers ----------------
__device__ __forceinline__ unsigned fkey(float f) {
    unsigned u = __float_as_uint(f);
    return (u >> 31) ? ~u : (u | 0x80000000u);   // monotone: smaller float -> smaller key
}
__device__ __forceinline__ float unfkey(unsigned k) {
    return (k & 0x80000000u) ? __uint_as_float(k & 0x7FFFFFFFu) : __uint_as_float(~k);
}

// ---------------- jax.image.resize (linear, antialias=False) fp-exact taps ----------------
struct Tap { int i0; float w0, w1; };

__device__ __forceinline__ float samplef(int o, float inv) {
    return __fsub_rn(__fmul_rn(__fadd_rn((float)o, 0.5f), inv), 0.5f);
}

__device__ __forceinline__ Tap make_tap(float s, int n) {
    Tap t;
    float fs = floorf(s);
    int i0 = (int)fs;
    if (i0 < 0)            { t.i0 = 0;     t.w0 = 1.f; t.w1 = 0.f; }
    else if (i0 >= n - 1)  { t.i0 = n - 2; t.w0 = 0.f; t.w1 = 1.f; }
    else {
        float w0  = __fsub_rn(1.0f, __fsub_rn(s, fs));
        float w1  = __fsub_rn(1.0f, __fsub_rn((float)(i0 + 1), s));
        float sum = __fadd_rn(w0, w1);
        if (sum != 1.0f) { w0 = __fdiv_rn(w0, sum); w1 = __fdiv_rn(w1, sum); }
        t.i0 = i0; t.w0 = w0; t.w1 = w1;
    }
    return t;
}

// P(r,c) with the exact k_prep expression (bit-identical wherever computed)
__device__ __forceinline__ float p_val(int pr, int pc) {
    float4 tyr = d_xt1[pr];
    float4 txc = d_xt1[pc];
    int yi = __float_as_int(tyr.x);
    int xi = __float_as_int(txc.x);
    const float* s0 = d_sim + yi * FEAT;
    float cy0 = fmaf(tyr.z, s0[FEAT + xi],     __fmul_rn(tyr.y, s0[xi]));
    float cy1 = fmaf(tyr.z, s0[FEAT + xi + 1], __fmul_rn(tyr.y, s0[xi + 1]));
    return fmaf(txc.z, cy1, __fmul_rn(txc.y, cy0));
}

// ---------------- kernel 1: sim (8-way channel split) + all tap tables + init ----------------
__global__ void __launch_bounds__(256) k_simtab(const float* __restrict__ emb,
                                                const float* __restrict__ ref,
                                                const int* __restrict__ ori) {
    int t = threadIdx.x;
    if (blockIdx.x < 128) {
        __shared__ float sref[EMBC];
        __shared__ float sdot[256];
        __shared__ float snrm[256];
        sref[t] = ref[t];
        __syncthreads();

        int px = t & 31;
        int q  = t >> 5;                      // channel group 0..7
        int p  = (blockIdx.x << 5) + px;      // feature pixel
        const float* e = emb + (q * 32) * (FEAT * FEAT) + p;
        const float* r = sref + q * 32;
        float dot = 0.f, nrm = 0.f;
        #pragma unroll
        for (int j = 0; j < 32; j++) {
            float v = e[j * (FEAT * FEAT)];   // coalesced, 32 independent loads
            dot = fmaf(r[j], v, dot);
            nrm = fmaf(v, v, nrm);
        }
        sdot[t] = dot; snrm[t] = nrm;
        __syncthreads();

        if (t < 32) {
            float D = sdot[t], N = snrm[t];
            #pragma unroll
            for (int q2 = 1; q2 < 8; q2++) {  // fixed sequential order (deterministic)
                D += sdot[t + (q2 << 5)];
                N += snrm[t + (q2 << 5)];
            }
            d_sim[(blockIdx.x << 5) + t] = D / sqrtf(N);
        }
    } else {
        int idx = (blockIdx.x - 128) * 256 + t;   // 0..4095
        if (idx == 0) { d_minkey = ~0ull; d_counter = 0; }
        if (idx < NCELLS) d_cellkey[idx] = 0ull;

        if (idx < 1024) {                         // 64 -> 1024 taps (P rows and cols)
            Tap tp = make_tap(samplef(idx, 0.0625f), FEAT);
            d_xt1[idx] = make_float4(__int_as_float(tp.i0), tp.w0, tp.w1, 0.f);
        }
        int H = ori[0], W = ori[1];
        int mx = max(H, W);
        double scale = (double)IMGSZ / (double)mx;
        int ph = (int)floor((double)H * scale + 0.5);
        int pw = (int)floor((double)W * scale + 0.5);
        float invx = (float)(1.0 / ((double)W / (double)pw));
        float invy = (float)(1.0 / ((double)H / (double)ph));
        float r64  = (float)(scale / 64.0);
        if (idx < W) {                            // scan x-taps (pw -> W)
            Tap tp = make_tap(samplef(idx, invx), pw);
            d_xtab[idx] = make_float4(__int_as_float(tp.i0), tp.w0, tp.w1, 0.f);
        }
        if (idx < H) {                            // scan y-taps (ph -> H) + gy16
            Tap tp = make_tap(samplef(idx, invy), ph);
            int gy16 = 16 * (int)floorf(__fmul_rn((float)idx, r64));
            d_ytab[idx] = make_float4(__int_as_float(tp.i0), tp.w0, tp.w1,
                                      __int_as_float(gy16));
        }
    }
}

// ---------------- kernel 2: fused P-tile + column scan + finalize ----------------
// Hot loop: 4 independent min chains + per-thread max (FMNMX); threshold atomics
// moved to a rare out-of-line second pass over the same smem tile.
__global__ void __launch_bounds__(256, 6) k_scan(const int* __restrict__ ori,
                                                 float* __restrict__ out) {
    int H = ori[0], W = ori[1];
    int mx = max(H, W);
    double scale = (double)IMGSZ / (double)mx;
    float r64  = (float)(scale / 64.0);

    __shared__ float2 tile2[TILE_R][TILE_C];   // {P(r,c), P(r,c+1)} pairs
    __shared__ float4 s_yt[YCHUNK];            // staged y-taps for this strip

    int t  = threadIdx.x;
    int xs = blockIdx.x * 256;
    int nby = gridDim.y;
    int chn = (H + nby - 1) / nby;             // <= YCHUNK
    int ys = blockIdx.y * chn;
    int ye = min(H, ys + chn);

    unsigned long long localkey = ~0ull;

    if (ys < H && xs < W) {
        int ny = ye - ys;
        int xe = min(xs + 256, W);
        // P-tile bounds this block needs (monotone tap tables)
        int pr0 = __float_as_int(d_ytab[ys].x);
        int pr1 = __float_as_int(d_ytab[ye - 1].x) + 1;
        int px0 = __float_as_int(d_xtab[xs].x);
        int px1 = __float_as_int(d_xtab[xe - 1].x) + 1;
        int NR = pr1 - pr0 + 1;            // <= 14
        int NC = px1 - px0 + 1;            // <= 70

        // stage y-taps for this strip
        for (int i = t; i < ny; i += 256) s_yt[i] = d_ytab[ys + i];

        // build tile2: each entry holds (P(r,c), P(r,c+1)), exact expression
        int nbuild = NR * (NC - 1);
        for (int i = t; i < nbuild; i += 256) {
            int r = i / (NC - 1), c = i - r * (NC - 1);
            float v0 = p_val(pr0 + r, px0 + c);
            float v1 = p_val(pr0 + r, px0 + c + 1);
            tile2[r][c] = make_float2(v0, v1);
        }
        __syncthreads();

        int x = xs + t;
        if (x < W) {
            float4 tx = d_xtab[x];
            int   lx  = __float_as_int(tx.x) - px0;
            float wx0 = tx.y, wx1 = tx.z;

            // 4 independent min chains + one max chain (no branches in hot loop)
            float rb0 = INFINITY, rb1 = INFINITY, rb2 = INFINITY, rb3 = INFINITY;
            int   ri0 = 0, ri1 = 0, ri2 = 0, ri3 = 0;
            float rmax = -INFINITY;

            int idx0 = ys * W + x;
            int i = 0;
            for (; i + 3 < ny; i += 4) {
                #pragma unroll
                for (int j = 0; j < 4; j++) {
                    float4 ty = s_yt[i + j];
                    int lr = __float_as_int(ty.x) - pr0;
                    float2 A = tile2[lr][lx];
                    float2 B = tile2[lr + 1][lx];
                    float c0 = fmaf(ty.z, B.x, __fmul_rn(ty.y, A.x));
                    float c1 = fmaf(ty.z, B.y, __fmul_rn(ty.y, A.y));
                    float v  = fmaf(wx1, c1, __fmul_rn(wx0, c0));
                    int  idx = idx0 + j * W;

                    if (j == 0) { if (v < rb0) { rb0 = v; ri0 = idx; } }
                    if (j == 1) { if (v < rb1) { rb1 = v; ri1 = idx; } }
                    if (j == 2) { if (v < rb2) { rb2 = v; ri2 = idx; } }
                    if (j == 3) { if (v < rb3) { rb3 = v; ri3 = idx; } }
                    rmax = fmaxf(rmax, v);
                }
                idx0 += 4 * W;
            }
            for (; i < ny; i++) {                // remainder -> chain 0
                float4 ty = s_yt[i];
                int lr = __float_as_int(ty.x) - pr0;
                float2 A = tile2[lr][lx];
                float2 B = tile2[lr + 1][lx];
                float c0 = fmaf(ty.z, B.x, __fmul_rn(ty.y, A.x));
                float c1 = fmaf(ty.z, B.y, __fmul_rn(ty.y, A.y));
                float v  = fmaf(wx1, c1, __fmul_rn(wx0, c0));
                if (v < rb0) { rb0 = v; ri0 = idx0; }
                rmax = fmaxf(rmax, v);
                idx0 += W;
            }

            // merge chains via packed keys: bit-equal values -> lowest index wins
            unsigned long long k0 = ((unsigned long long)fkey(rb0) << 32) | (unsigned)ri0;
            unsigned long long k1 = ((unsigned long long)fkey(rb1) << 32) | (unsigned)ri1;
            unsigned long long k2 = ((unsigned long long)fkey(rb2) << 32) | (unsigned)ri2;
            unsigned long long k3 = ((unsigned long long)fkey(rb3) << 32) | (unsigned)ri3;
            localkey = min(min(k0, k1), min(k2, k3));

            // rare slow path: this thread saw a value over THRESH -> redo with atomics
            if (rmax > THRESH) {
                int gx = (int)floorf(__fmul_rn((float)x, r64));
                int idx = ys * W + x;
                for (int k = 0; k < ny; k++) {
                    float4 ty = s_yt[k];
                    int lr = __float_as_int(ty.x) - pr0;
                    float2 A = tile2[lr][lx];
                    float2 B = tile2[lr + 1][lx];
                    float c0 = fmaf(ty.z, B.x, __fmul_rn(ty.y, A.x));
                    float c1 = fmaf(ty.z, B.y, __fmul_rn(ty.y, A.y));
                    float v  = fmaf(wx1, c1, __fmul_rn(wx0, c0));
                    if (v > THRESH) {            // identical values, identical atomics
                        int cell = __float_as_int(ty.w) + gx;
                        unsigned long long ck = ((unsigned long long)fkey(v) << 32)
                                              | (unsigned)(0xFFFFFFFFu - (unsigned)idx);
                        atomicMax(&d_cellkey[cell], ck);
                    }
                    idx += W;
                }
            }
        }
    }

    // block argmin reduction
    __shared__ unsigned long long sk[256];
    __shared__ int s_last;
    sk[t] = localkey;
    __syncthreads();
    for (int o = 128; o > 0; o >>= 1) {
        if (t < o) sk[t] = min(sk[t], sk[t + o]);
        __syncthreads();
    }
    if (t == 0) {
        atomicMin(&d_minkey, sk[0]);
        __threadfence();
        s_last = (atomicAdd(&d_counter, 1) == (int)(gridDim.x * gridDim.y) - 1);
    }
    __syncthreads();
    if (!s_last) return;

    // ---- last block: finalize ----
    __shared__ float s_key[NCELLS];
    unsigned long long ck = atomicOr(&d_cellkey[t], 0ull);    // coherent read
    bool valid = (ck != 0ull);
    float ps = 0.f; int pidx = 0;
    if (valid) {
        ps   = unfkey((unsigned)(ck >> 32));
        pidx = (int)(0xFFFFFFFFu - (unsigned)(ck & 0xFFFFFFFFull));
    }
    float skey = valid ? ps : -INFINITY;
    s_key[t] = skey;
    __syncthreads();

    int rank = 0;
    #pragma unroll 8
    for (int j = 0; j < NCELLS; j++) {
        float o = s_key[j];
        rank += (o > skey) || (o == skey && j < t);
    }

    out[rank * 3 + 0] = valid ? (float)(pidx % W) : -1.f;
    out[rank * 3 + 1] = valid ? (float)(pidx / W) : -1.f;
    out[rank * 3 + 2] = valid ? ps : -1.f;

    if (t == 0) {
        unsigned long long mk = atomicOr(&d_minkey, 0ull);
        unsigned bidx = (unsigned)(mk & 0xFFFFFFFFull);
        out[NCELLS * 3 + 0] = (float)(bidx % (unsigned)W);   // bg col (x)
        out[NCELLS * 3 + 1] = (float)(bidx / (unsigned)W);   // bg row (y)
    }
}

// ---------------- launch ----------------
extern "C" void kernel_launch(void* const* d_in, const int* in_sizes, int n_in,
                              void* d_out, int out_size) {
    int ie = 0, ir = 1, io = 2;
    for (int i = 0; i < n_in; i++) {
        if (in_sizes[i] == 2) io = i;
        else if (in_sizes[i] == EMBC) ir = i;
        else ie = i;
    }
    const float* emb = (const float*)d_in[ie];
    const float* ref = (const float*)d_in[ir];
    const int*   ori = (const int*)d_in[io];
    float* out = (float*)d_out;

    k_simtab<<<144, 256>>>(emb, ref, ori);
    k_scan  <<<dim3(SCAN_BX, SCAN_BY), 256>>>(ori, out);
}